// round 8
// baseline (speedup 1.0000x reference)
#include <cuda_runtime.h>
#include <cstdint>

#define NMAX 4096
#define HID 64

typedef unsigned long long ull;

// ---------------- device scratch ----------------
__device__ __align__(256) float g_P[NMAX * HID];
__device__ __align__(256) float g_agg[NMAX * HID];
__device__ __align__(256) float g_q[4 * NMAX * 16];
__device__ __align__(256) float g_k[4 * NMAX * 16];
__device__ __align__(256) float g_v[4 * NMAX * 16];
__device__ __align__(256) float g_obuf[NMAX * HID];
__device__ __align__(256) ull g_wgdup[64 * 64];  // [k][d] = pack2(w2[d][k]*g[k], same)
__device__ __align__(256) float g_A[64];         // A[d] = sum_k w2[d][k]*g[k]
__device__ __align__(256) float g_Bc[64];        // B[d] + b2[d]
__device__ int g_is64_ei;
__device__ int g_is64_ty;

__device__ __forceinline__ long ldidx(const void* p, long i, int is64) {
    return is64 ? (long)((const long long*)p)[i] : (long)((const int*)p)[i];
}

// ---------------- packed f32x2 helpers ----------------
__device__ __forceinline__ ull pack2(float lo, float hi) {
    ull r; asm("mov.b64 %0, {%1, %2};" : "=l"(r) : "f"(lo), "f"(hi)); return r;
}
__device__ __forceinline__ void unpack2(ull v, float& lo, float& hi) {
    asm("mov.b64 {%0, %1}, %2;" : "=f"(lo), "=f"(hi) : "l"(v));
}
__device__ __forceinline__ void ffma2(ull& d, ull a, ull b) {
    asm("fma.rn.f32x2 %0, %1, %2, %0;" : "+l"(d) : "l"(a), "l"(b));
}
__device__ __forceinline__ ull mul2(ull a, ull b) {
    ull r; asm("mul.rn.f32x2 %0, %1, %2;" : "=l"(r) : "l"(a), "l"(b)); return r;
}

// ---------------- detect dtypes + per-dim LN1-fold constants ----------------
__global__ void detectAB_kernel(const unsigned* ei, const unsigned* ty,
                                const float* __restrict__ w2g,
                                const float* __restrict__ lng,
                                const float* __restrict__ lnb,
                                const float* __restrict__ b2) {
    int d = threadIdx.x;   // 64
    float A = 0.f, B = 0.f;
#pragma unroll 8
    for (int k = 0; k < 64; k++) {
        float w = w2g[d * 64 + k];
        A = fmaf(w, lng[k], A);
        B = fmaf(w, lnb[k], B);
    }
    g_A[d] = A;
    g_Bc[d] = B + b2[d];
    if (d == 0) {
        unsigned a = 0;
        for (int i = 0; i < 32; i++) a |= ei[2 * i + 1];
        g_is64_ei = (a == 0) ? 1 : 0;
        unsigned b = 0;
        for (int i = 0; i < 32; i++) b |= ty[2 * i + 1];
        g_is64_ty = (b == 0) ? 1 : 0;
    }
}

// ---------------- fused setup: zero g_agg | dup-pack w*g | prep P -----------
__global__ void __launch_bounds__(256) setup_kernel(
    const float* __restrict__ x, const float* __restrict__ emb,
    const float* __restrict__ w1, const float* __restrict__ b1,
    const void* __restrict__ ety, const float* __restrict__ w2g,
    const float* __restrict__ lng, int N) {
    int bid = blockIdx.x, t = threadIdx.x;
    int zb = N / 16;
    if (bid < zb) {
        ((float4*)g_agg)[bid * 256 + t] = make_float4(0.f, 0.f, 0.f, 0.f);
    } else if (bid < zb + 16) {
        int i = (bid - zb) * 256 + t;        // i = k*64 + d
        int k = i >> 6, d = i & 63;
        float w = w2g[d * 64 + k] * lng[k];
        g_wgdup[i] = pack2(w, w);
    } else {
        int nb = bid - zb - 16;
        int grp = t >> 6, d = t & 63;
        int n = nb * 4 + grp;
        __shared__ float xs[4][16];
        int is64 = g_is64_ty;
        if (d < 6) {
            xs[grp][d] = x[n * 6 + d];
        } else if (d < 14) {
            long tt = ldidx(ety, n, is64);
            xs[grp][d] = emb[tt * 8 + (d - 6)];
        }
        __syncthreads();
        float acc = b1[d];
#pragma unroll
        for (int k = 0; k < 14; k++) acc = fmaf(xs[grp][k], w1[d * 15 + k], acc);
        g_P[n * HID + d] = acc;
    }
}

// ---------------- edge MLP + scatter-add ------------------------------------
// 128 threads / 128 edges. Stage B tiling: warp = 16-dim group with weights
// pre-duplicated in smem and read WARP-UNIFORM (broadcast LDS, zero MOVs);
// lane = 4-edge group (1 coalesced LDS.128 of h pairs per k).
#define EDGE_DYN (32768 + 32768)
__global__ void __launch_bounds__(128, 3) edge_kernel(
    const void* __restrict__ ei, const float* __restrict__ eattr,
    const float* __restrict__ w1, const float* __restrict__ lng,
    const float* __restrict__ lnb, int nE) {
    extern __shared__ __align__(16) char dyn[];
    float* h1f = (float*)dyn;                 // 32KB [k][128]; overlaid later
    ull* w2s = (ull*)(dyn + 32768);           // 32KB [k][64] dup-packed w*g
    __shared__ __align__(16) float w1ls[64];
    __shared__ __align__(16) float As[64];
    __shared__ __align__(16) float Bcs[64];
    __shared__ __align__(16) float gs[64];
    __shared__ __align__(16) float bs[64];
    __shared__ __align__(8) float rst[128 * 2];
    __shared__ int sdst[128];

    int tid = threadIdx.x;
    {   // stage dup-packed weights: 2048 ulonglong2 over 128 threads
        const ulonglong2* wsrc = (const ulonglong2*)g_wgdup;
        ulonglong2* wdst = (ulonglong2*)w2s;
#pragma unroll
        for (int i = 0; i < 16; i++) wdst[i * 128 + tid] = wsrc[i * 128 + tid];
    }
    if (tid < 64) {
        w1ls[tid] = w1[tid * 15 + 14];
        As[tid] = g_A[tid];
        Bcs[tid] = g_Bc[tid];
        gs[tid] = lng[tid];
        bs[tid] = lnb[tid];
    }
    long e = (long)blockIdx.x * 128 + tid;
    bool act = e < nE;
    int is64 = g_is64_ei;
    long src = 0;
    float a = 0.f;
    {
        long dl = -1;
        if (act) {
            src = ldidx(ei, e, is64);
            dl = ldidx(ei, (long)nE + e, is64);
            a = eattr[e];
        }
        sdst[tid] = (int)dl;
    }
    __syncthreads();

    // ---- Stage A: x = relu(P[src] + a*w1_last); stats; raw x -> smem ----
    {
        const float4* pr = (const float4*)(g_P + src * 64);
        float s1 = 0.f, q1 = 0.f;
#pragma unroll
        for (int g = 0; g < 16; g++) {
            float4 p = pr[g];
            float4 wl = ((const float4*)w1ls)[g];
            float x0 = fmaxf(fmaf(a, wl.x, p.x), 0.f);
            float x1 = fmaxf(fmaf(a, wl.y, p.y), 0.f);
            float x2 = fmaxf(fmaf(a, wl.z, p.z), 0.f);
            float x3 = fmaxf(fmaf(a, wl.w, p.w), 0.f);
            h1f[(4 * g + 0) * 128 + tid] = x0;
            h1f[(4 * g + 1) * 128 + tid] = x1;
            h1f[(4 * g + 2) * 128 + tid] = x2;
            h1f[(4 * g + 3) * 128 + tid] = x3;
            s1 += (x0 + x1) + (x2 + x3);
            q1 = fmaf(x0, x0, q1); q1 = fmaf(x1, x1, q1);
            q1 = fmaf(x2, x2, q1); q1 = fmaf(x3, x3, q1);
        }
        float mean1 = s1 * (1.f / 64.f);
        float var1 = fmaf(-mean1, mean1, q1 * (1.f / 64.f));
        float r1 = rsqrtf(var1 + 1e-5f);
        rst[2 * tid] = r1;
        rst[2 * tid + 1] = -mean1 * r1;
    }
    __syncthreads();

    // ---- Stage B: warp=16 dims (broadcast dup-weights), lane=4 edges ----
    int lane = tid & 31, wrp = tid >> 5;
    ull acc[2][16];
#pragma unroll
    for (int pp = 0; pp < 2; pp++)
#pragma unroll
        for (int j = 0; j < 16; j++) acc[pp][j] = 0ull;
    {
        const ulonglong2* hb2 = (const ulonglong2*)h1f;
        const ull* wbase = w2s + wrp * 16;
#pragma unroll 8
        for (int k = 0; k < 64; k++) {
            ulonglong2 hp = hb2[k * 32 + lane];    // edges 4*lane..+3 (2 pairs)
            const ulonglong2* wk = (const ulonglong2*)(wbase + k * 64);
            ulonglong2 w0 = wk[0], w1v = wk[1], w2v = wk[2], w3 = wk[3];
            ulonglong2 w4 = wk[4], w5 = wk[5], w6 = wk[6], w7 = wk[7];
            ffma2(acc[0][0], w0.x, hp.x);  ffma2(acc[1][0], w0.x, hp.y);
            ffma2(acc[0][1], w0.y, hp.x);  ffma2(acc[1][1], w0.y, hp.y);
            ffma2(acc[0][2], w1v.x, hp.x); ffma2(acc[1][2], w1v.x, hp.y);
            ffma2(acc[0][3], w1v.y, hp.x); ffma2(acc[1][3], w1v.y, hp.y);
            ffma2(acc[0][4], w2v.x, hp.x); ffma2(acc[1][4], w2v.x, hp.y);
            ffma2(acc[0][5], w2v.y, hp.x); ffma2(acc[1][5], w2v.y, hp.y);
            ffma2(acc[0][6], w3.x, hp.x);  ffma2(acc[1][6], w3.x, hp.y);
            ffma2(acc[0][7], w3.y, hp.x);  ffma2(acc[1][7], w3.y, hp.y);
            ffma2(acc[0][8], w4.x, hp.x);  ffma2(acc[1][8], w4.x, hp.y);
            ffma2(acc[0][9], w4.y, hp.x);  ffma2(acc[1][9], w4.y, hp.y);
            ffma2(acc[0][10], w5.x, hp.x); ffma2(acc[1][10], w5.x, hp.y);
            ffma2(acc[0][11], w5.y, hp.x); ffma2(acc[1][11], w5.y, hp.y);
            ffma2(acc[0][12], w6.x, hp.x); ffma2(acc[1][12], w6.x, hp.y);
            ffma2(acc[0][13], w6.y, hp.x); ffma2(acc[1][13], w6.y, hp.y);
            ffma2(acc[0][14], w7.x, hp.x); ffma2(acc[1][14], w7.x, hp.y);
            ffma2(acc[0][15], w7.y, hp.x); ffma2(acc[1][15], w7.y, hp.y);
        }
    }

    // ---- Stage C: fold LN1 consts, stats, LN2, scatter ----
    float Ar[16], Br[16];
    {
        const float4* ap = (const float4*)(As + wrp * 16);
        const float4* bp = (const float4*)(Bcs + wrp * 16);
#pragma unroll
        for (int u = 0; u < 4; u++) {
            float4 av = ap[u], bv = bp[u];
            Ar[4 * u] = av.x; Ar[4 * u + 1] = av.y; Ar[4 * u + 2] = av.z; Ar[4 * u + 3] = av.w;
            Br[4 * u] = bv.x; Br[4 * u + 1] = bv.y; Br[4 * u + 2] = bv.z; Br[4 * u + 3] = bv.w;
        }
    }
    float rr[4], mm[4];
    int dn[4];
#pragma unroll
    for (int i = 0; i < 4; i++) {
        rr[i] = rst[2 * (4 * lane + i)];
        mm[i] = rst[2 * (4 * lane + i) + 1];
        dn[i] = sdst[4 * lane + i];
    }
    float vv[4][16];
    float se[4] = {0.f, 0.f, 0.f, 0.f}, qe[4] = {0.f, 0.f, 0.f, 0.f};
#pragma unroll
    for (int pp = 0; pp < 2; pp++) {
#pragma unroll
        for (int j = 0; j < 16; j++) {
            float lo, hi;
            unpack2(acc[pp][j], lo, hi);
            float b0 = fmaf(mm[2 * pp], Ar[j], Br[j]);
            float b1 = fmaf(mm[2 * pp + 1], Ar[j], Br[j]);
            float v0 = fmaxf(fmaf(rr[2 * pp], lo, b0), 0.f);
            float v1 = fmaxf(fmaf(rr[2 * pp + 1], hi, b1), 0.f);
            vv[2 * pp][j] = v0;
            vv[2 * pp + 1][j] = v1;
            se[2 * pp] += v0; qe[2 * pp] = fmaf(v0, v0, qe[2 * pp]);
            se[2 * pp + 1] += v1; qe[2 * pp + 1] = fmaf(v1, v1, qe[2 * pp + 1]);
        }
    }
    __syncthreads();   // h1f reads done; overlay partials
    float* ps = h1f;            // [4][128]
    float* pq = h1f + 512;      // [4][128]
#pragma unroll
    for (int i = 0; i < 4; i++) {
        ps[wrp * 128 + 4 * lane + i] = se[i];
        pq[wrp * 128 + 4 * lane + i] = qe[i];
    }
    __syncthreads();
    {
        float s = ps[tid] + ps[128 + tid] + ps[256 + tid] + ps[384 + tid];
        float q = pq[tid] + pq[128 + tid] + pq[256 + tid] + pq[384 + tid];
        float mean = s * (1.f / 64.f);
        float var = fmaf(-mean, mean, q * (1.f / 64.f));
        float r = rsqrtf(var + 1e-5f);
        rst[2 * tid] = r;
        rst[2 * tid + 1] = -mean * r;
    }
    __syncthreads();
    float gr[16], br[16];
    {
        const float4* gp = (const float4*)(gs + wrp * 16);
        const float4* bp = (const float4*)(bs + wrp * 16);
#pragma unroll
        for (int u = 0; u < 4; u++) {
            float4 gv = gp[u], bv = bp[u];
            gr[4 * u] = gv.x; gr[4 * u + 1] = gv.y; gr[4 * u + 2] = gv.z; gr[4 * u + 3] = gv.w;
            br[4 * u] = bv.x; br[4 * u + 1] = bv.y; br[4 * u + 2] = bv.z; br[4 * u + 3] = bv.w;
        }
    }
#pragma unroll
    for (int i = 0; i < 4; i++) {
        float r2 = rst[2 * (4 * lane + i)];
        float mr2 = rst[2 * (4 * lane + i) + 1];
        if (dn[i] >= 0) {
            float* p = g_agg + (long)dn[i] * 64 + wrp * 16;
#pragma unroll
            for (int u = 0; u < 4; u++) {
                float o0 = fmaf(fmaf(vv[i][4 * u], r2, mr2), gr[4 * u], br[4 * u]);
                float o1 = fmaf(fmaf(vv[i][4 * u + 1], r2, mr2), gr[4 * u + 1], br[4 * u + 1]);
                float o2 = fmaf(fmaf(vv[i][4 * u + 2], r2, mr2), gr[4 * u + 2], br[4 * u + 2]);
                float o3 = fmaf(fmaf(vv[i][4 * u + 3], r2, mr2), gr[4 * u + 3], br[4 * u + 3]);
                asm volatile("red.global.add.v4.f32 [%0], {%1,%2,%3,%4};"
                             :: "l"(p + 4 * u), "f"(o0), "f"(o1), "f"(o2), "f"(o3)
                             : "memory");
            }
        }
    }
}

// ---------------- qkv = h @ in_proj_w.T + b, 32 nodes/block ------------------
__global__ void __launch_bounds__(192) qkv_kernel(const float* __restrict__ w,
                                                  const float* __restrict__ b, int N) {
    __shared__ __align__(16) float hs[32 * 64];
    int tid = threadIdx.x;
    int n0 = blockIdx.x * 32;
    for (int i = tid; i < 32 * 64 / 4; i += 192)
        ((float4*)hs)[i] = ((const float4*)(g_agg + n0 * 64))[i];
    float wr[64];
    {
        const float4* p4 = (const float4*)(w + tid * 64);
#pragma unroll
        for (int k = 0; k < 16; k++) {
            float4 f = p4[k];
            wr[4 * k] = f.x; wr[4 * k + 1] = f.y; wr[4 * k + 2] = f.z; wr[4 * k + 3] = f.w;
        }
    }
    float br = b[tid];
    __syncthreads();
    int sec = tid / 64, wi = tid % 64, hh = wi / 16, dd = wi % 16;
    float* dst = sec == 0 ? g_q : (sec == 1 ? g_k : g_v);
#pragma unroll 4
    for (int nn = 0; nn < 32; nn++) {
        float acc = br;
#pragma unroll
        for (int k = 0; k < 16; k++) {
            float4 h = *(const float4*)&hs[nn * 64 + 4 * k];
            acc = fmaf(wr[4 * k], h.x, acc);
            acc = fmaf(wr[4 * k + 1], h.y, acc);
            acc = fmaf(wr[4 * k + 2], h.z, acc);
            acc = fmaf(wr[4 * k + 3], h.w, acc);
        }
        dst[hh * N * 16 + (n0 + nn) * 16 + dd] = acc;
    }
}

// ---------------- flash attention, f32x2, chunked branchless rescale --------
__global__ void __launch_bounds__(128) attn_kernel(int N) {
    int hh = blockIdx.y;
    int part = threadIdx.x >> 5;
    int lane = threadIdx.x & 31;
    int qi = blockIdx.x * 32 + lane;
    const float* Q = g_q + hh * N * 16;
    const float* K = g_k + hh * N * 16;
    const float* V = g_v + hh * N * 16;

    __shared__ __align__(16) float Ks[4][64 * 16];
    __shared__ __align__(16) float Vs[4][64 * 16];
    __shared__ float mrg[3][32][18];

    ull q2[8];
    {
        const float4* qp = (const float4*)(Q + qi * 16);
#pragma unroll
        for (int u = 0; u < 4; u++) {
            float4 f = qp[u];
            q2[2 * u] = pack2(f.x * 0.25f, f.y * 0.25f);
            q2[2 * u + 1] = pack2(f.z * 0.25f, f.w * 0.25f);
        }
    }
    ull o2[8];
#pragma unroll
    for (int u = 0; u < 8; u++) o2[u] = 0ull;
    float m = -1e30f, l = 0.f;

    int j0 = part * (N >> 2);
    for (int kt = 0; kt < (N >> 2); kt += 64) {
        {
            const float4* ksrc = (const float4*)(K + (j0 + kt) * 16);
            const float4* vsrc = (const float4*)(V + (j0 + kt) * 16);
            float4* kdst = (float4*)Ks[part];
            float4* vdst = (float4*)Vs[part];
#pragma unroll
            for (int u = 0; u < 8; u++) {
                kdst[u * 32 + lane] = ksrc[u * 32 + lane];
                vdst[u * 32 + lane] = vsrc[u * 32 + lane];
            }
        }
        __syncwarp();
        for (int c = 0; c < 4; c++) {
            float s[16];
#pragma unroll
            for (int jj = 0; jj < 16; jj++) {
                int j = c * 16 + jj;
                const ulonglong2* kr = (const ulonglong2*)&Ks[part][j * 16];
                ulonglong2 ka = kr[0], kb = kr[1], kc = kr[2], kd = kr[3];
                ull s2 = mul2(q2[0], ka.x);
                ffma2(s2, q2[1], ka.y);
                ffma2(s2, q2[2], kb.x);
                ffma2(s2, q2[3], kb.y);
                ffma2(s2, q2[4], kc.x);
                ffma2(s2, q2[5], kc.y);
                ffma2(s2, q2[6], kd.x);
                ffma2(s2, q2[7], kd.y);
                float slo, shi;
                unpack2(s2, slo, shi);
                s[jj] = slo + shi;
            }
            float tm = s[0];
#pragma unroll
            for (int jj = 1; jj < 16; jj++) tm = fmaxf(tm, s[jj]);
            float nm = fmaxf(m, tm);
            float corr = __expf(m - nm);
            m = nm;
            l *= corr;
            ull c2 = pack2(corr, corr);
#pragma unroll
            for (int u = 0; u < 8; u++) o2[u] = mul2(o2[u], c2);
#pragma unroll
            for (int jj = 0; jj < 16; jj++) {
                int j = c * 16 + jj;
                float p = __expf(s[jj] - m);
                l += p;
                ull p2 = pack2(p, p);
                const ulonglong2* vr = (const ulonglong2*)&Vs[part][j * 16];
                ulonglong2 va = vr[0], vb = vr[1], vc = vr[2], vd = vr[3];
                ffma2(o2[0], p2, va.x);
                ffma2(o2[1], p2, va.y);
                ffma2(o2[2], p2, vb.x);
                ffma2(o2[3], p2, vb.y);
                ffma2(o2[4], p2, vc.x);
                ffma2(o2[5], p2, vc.y);
                ffma2(o2[6], p2, vd.x);
                ffma2(o2[7], p2, vd.y);
            }
        }
        __syncwarp();
    }

    if (part != 0) {
        float* d = &mrg[part - 1][lane][0];
        d[0] = m;
        d[1] = l;
#pragma unroll
        for (int u = 0; u < 8; u++) {
            float lo, hi;
            unpack2(o2[u], lo, hi);
            d[2 + 2 * u] = lo;
            d[3 + 2 * u] = hi;
        }
    }
    __syncthreads();
    if (part == 0) {
        float M = m;
#pragma unroll
        for (int p2i = 0; p2i < 3; p2i++) M = fmaxf(M, mrg[p2i][lane][0]);
        float c0 = __expf(m - M);
        float L = l * c0;
        float o[16];
#pragma unroll
        for (int u = 0; u < 8; u++) {
            float lo, hi;
            unpack2(o2[u], lo, hi);
            o[2 * u] = lo * c0;
            o[2 * u + 1] = hi * c0;
        }
#pragma unroll
        for (int p2i = 0; p2i < 3; p2i++) {
            const float* sp = &mrg[p2i][lane][0];
            float cp = __expf(sp[0] - M);
            L = fmaf(sp[1], cp, L);
#pragma unroll
            for (int c = 0; c < 16; c++) o[c] = fmaf(sp[2 + c], cp, o[c]);
        }
        float inv = 1.f / L;
#pragma unroll
        for (int c = 0; c < 16; c++) g_obuf[qi * 64 + hh * 16 + c] = o[c] * inv;
    }
}

// ---------------- out_proj + residual + LN + final linear --------------------
__global__ void __launch_bounds__(128) epi_kernel(
    const float* __restrict__ opw, const float* __restrict__ opb,
    const float* __restrict__ ang, const float* __restrict__ anb,
    const float* __restrict__ ow, const float* __restrict__ ob,
    float* __restrict__ out) {
    int tid = threadIdx.x;
    int d = tid & 63, g = tid >> 6;
    int n0 = blockIdx.x * 8;
    __shared__ __align__(16) float os[8 * 64];
    __shared__ __align__(16) float ts[8 * 64];
    __shared__ float ps[8][16], pq[8][16];
    __shared__ float mv[8][2];

    for (int i = tid; i < 8 * 64; i += 128) os[i] = g_obuf[n0 * 64 + i];
    float wr[64];
    {
        const float4* p4 = (const float4*)(opw + d * 64);
#pragma unroll
        for (int k = 0; k < 16; k++) {
            float4 f = p4[k];
            wr[4 * k] = f.x; wr[4 * k + 1] = f.y; wr[4 * k + 2] = f.z; wr[4 * k + 3] = f.w;
        }
    }
    float bb = opb[d];
    __syncthreads();
#pragma unroll
    for (int ni = 0; ni < 4; ni++) {
        int nn = g * 4 + ni;
        float acc = bb;
#pragma unroll
        for (int k = 0; k < 16; k++) {
            float4 h = *(const float4*)&os[nn * 64 + 4 * k];
            acc = fmaf(wr[4 * k], h.x, acc);
            acc = fmaf(wr[4 * k + 1], h.y, acc);
            acc = fmaf(wr[4 * k + 2], h.z, acc);
            acc = fmaf(wr[4 * k + 3], h.w, acc);
        }
        ts[nn * 64 + d] = g_agg[(n0 + nn) * 64 + d] + acc;
    }
    __syncthreads();
    {
        int n = tid >> 4, sg = tid & 15;
        float s = 0.f, qq = 0.f;
#pragma unroll
        for (int t = 0; t < 4; t++) {
            float v2 = ts[n * 64 + sg * 4 + t];
            s += v2; qq += v2 * v2;
        }
        ps[n][sg] = s; pq[n][sg] = qq;
    }
    __syncthreads();
    if (tid < 8) {
        float s = 0.f, qq = 0.f;
#pragma unroll
        for (int t = 0; t < 16; t++) { s += ps[tid][t]; qq += pq[tid][t]; }
        float mean = s * (1.f / 64.f);
        float var = qq * (1.f / 64.f) - mean * mean;
        mv[tid][0] = mean;
        mv[tid][1] = rsqrtf(var + 1e-5f);
    }
    __syncthreads();
    float gg = ang[d], gb = anb[d];
#pragma unroll
    for (int ni = 0; ni < 4; ni++) {
        int nn = g * 4 + ni;
        ts[nn * 64 + d] = (ts[nn * 64 + d] - mv[nn][0]) * mv[nn][1] * gg + gb;
    }
    {
        const float4* p4 = (const float4*)(ow + d * 64);
#pragma unroll
        for (int k = 0; k < 16; k++) {
            float4 f = p4[k];
            wr[4 * k] = f.x; wr[4 * k + 1] = f.y; wr[4 * k + 2] = f.z; wr[4 * k + 3] = f.w;
        }
    }
    float bo = ob[d];
    __syncthreads();
#pragma unroll
    for (int ni = 0; ni < 4; ni++) {
        int nn = g * 4 + ni;
        float acc = bo;
#pragma unroll
        for (int k = 0; k < 16; k++) {
            float4 h = *(const float4*)&ts[nn * 64 + 4 * k];
            acc = fmaf(wr[4 * k], h.x, acc);
            acc = fmaf(wr[4 * k + 1], h.y, acc);
            acc = fmaf(wr[4 * k + 2], h.z, acc);
            acc = fmaf(wr[4 * k + 3], h.w, acc);
        }
        out[(n0 + nn) * 64 + d] = acc;
    }
}

// ---------------- launch ----------------
extern "C" void kernel_launch(void* const* d_in, const int* in_sizes, int n_in,
                              void* d_out, int out_size) {
    const float* x        = (const float*)d_in[0];
    const float* eattr    = (const float*)d_in[1];
    const float* emb      = (const float*)d_in[2];
    const float* lin1_w   = (const float*)d_in[3];
    const float* lin1_b   = (const float*)d_in[4];
    const float* lay_w    = (const float*)d_in[5];
    const float* lay_b    = (const float*)d_in[6];
    const float* ln_g     = (const float*)d_in[7];
    const float* ln_b     = (const float*)d_in[8];
    const float* in_proj_w  = (const float*)d_in[9];
    const float* in_proj_b  = (const float*)d_in[10];
    const float* out_proj_w = (const float*)d_in[11];
    const float* out_proj_b = (const float*)d_in[12];
    const float* an_g     = (const float*)d_in[13];
    const float* an_b     = (const float*)d_in[14];
    const float* out_w    = (const float*)d_in[15];
    const float* out_b    = (const float*)d_in[16];
    const void*  ei       = d_in[17];
    const void*  ety      = d_in[18];

    int E = in_sizes[1];
    int N = in_sizes[0] / 6;

    cudaFuncSetAttribute(edge_kernel, cudaFuncAttributeMaxDynamicSharedMemorySize,
                         EDGE_DYN);

    detectAB_kernel<<<1, 64>>>((const unsigned*)ei, (const unsigned*)ety,
                               lay_w, ln_g, ln_b, lay_b);
    setup_kernel<<<N / 16 + 16 + N / 4, 256>>>(x, emb, lin1_w, lin1_b, ety,
                                               lay_w, ln_g, N);
    edge_kernel<<<(E + 127) / 128, 128, EDGE_DYN>>>(ei, eattr, lin1_w, ln_g,
                                                    ln_b, E);
    qkv_kernel<<<N / 32, 192>>>(in_proj_w, in_proj_b, N);
    attn_kernel<<<dim3(N / 32, 4), 128>>>(N);
    epi_kernel<<<N / 8, 128>>>(out_proj_w, out_proj_b, an_g, an_b, out_w, out_b,
                               (float*)d_out);
}

// round 9
// speedup vs baseline: 1.0936x; 1.0936x over previous
#include <cuda_runtime.h>
#include <cstdint>

#define NMAX 4096
#define HID 64

typedef unsigned long long ull;

// ---------------- device scratch ----------------
__device__ __align__(256) float g_P[NMAX * HID];
__device__ __align__(256) float g_agg[NMAX * HID];
__device__ __align__(256) float g_q[4 * NMAX * 16];
__device__ __align__(256) float g_k[4 * NMAX * 16];
__device__ __align__(256) float g_v[4 * NMAX * 16];
__device__ __align__(256) float g_obuf[NMAX * HID];
__device__ __align__(256) float g_wgk[64 * 64];  // [k][d] = w2[d][k]*g[k] (scalar)
__device__ __align__(256) float g_A[64];         // A[d] = sum_k w2[d][k]*g[k]
__device__ __align__(256) float g_Bc[64];        // B[d] + b2[d]
__device__ int g_is64_ei;
__device__ int g_is64_ty;

__device__ __forceinline__ long ldidx(const void* p, long i, int is64) {
    return is64 ? (long)((const long long*)p)[i] : (long)((const int*)p)[i];
}

// ---------------- packed f32x2 helpers ----------------
__device__ __forceinline__ ull pack2(float lo, float hi) {
    ull r; asm("mov.b64 %0, {%1, %2};" : "=l"(r) : "f"(lo), "f"(hi)); return r;
}
__device__ __forceinline__ void unpack2(ull v, float& lo, float& hi) {
    asm("mov.b64 {%0, %1}, %2;" : "=f"(lo), "=f"(hi) : "l"(v));
}
__device__ __forceinline__ void ffma2(ull& d, ull a, ull b) {
    asm("fma.rn.f32x2 %0, %1, %2, %0;" : "+l"(d) : "l"(a), "l"(b));
}
__device__ __forceinline__ ull mul2(ull a, ull b) {
    ull r; asm("mul.rn.f32x2 %0, %1, %2;" : "=l"(r) : "l"(a), "l"(b)); return r;
}

// ---------------- detect dtypes + per-dim LN1-fold constants ----------------
__global__ void detectAB_kernel(const unsigned* ei, const unsigned* ty,
                                const float* __restrict__ w2g,
                                const float* __restrict__ lng,
                                const float* __restrict__ lnb,
                                const float* __restrict__ b2) {
    int d = threadIdx.x;   // 64
    float A = 0.f, B = 0.f;
#pragma unroll 8
    for (int k = 0; k < 64; k++) {
        float w = w2g[d * 64 + k];
        A = fmaf(w, lng[k], A);
        B = fmaf(w, lnb[k], B);
    }
    g_A[d] = A;
    g_Bc[d] = B + b2[d];
    if (d == 0) {
        unsigned a = 0;
        for (int i = 0; i < 32; i++) a |= ei[2 * i + 1];
        g_is64_ei = (a == 0) ? 1 : 0;
        unsigned b = 0;
        for (int i = 0; i < 32; i++) b |= ty[2 * i + 1];
        g_is64_ty = (b == 0) ? 1 : 0;
    }
}

// ---------------- fused setup: zero g_agg | pack w*g k-major | prep P -------
__global__ void __launch_bounds__(256) setup_kernel(
    const float* __restrict__ x, const float* __restrict__ emb,
    const float* __restrict__ w1, const float* __restrict__ b1,
    const void* __restrict__ ety, const float* __restrict__ w2g,
    const float* __restrict__ lng, int N) {
    int bid = blockIdx.x, t = threadIdx.x;
    int zb = N / 16;
    if (bid < zb) {
        ((float4*)g_agg)[bid * 256 + t] = make_float4(0.f, 0.f, 0.f, 0.f);
    } else if (bid < zb + 16) {
        int i = (bid - zb) * 256 + t;        // i = k*64 + d
        int k = i >> 6, d = i & 63;
        g_wgk[i] = w2g[d * 64 + k] * lng[k];
    } else {
        int nb = bid - zb - 16;
        int grp = t >> 6, d = t & 63;
        int n = nb * 4 + grp;
        __shared__ float xs[4][16];
        int is64 = g_is64_ty;
        if (d < 6) {
            xs[grp][d] = x[n * 6 + d];
        } else if (d < 14) {
            long tt = ldidx(ety, n, is64);
            xs[grp][d] = emb[tt * 8 + (d - 6)];
        }
        __syncthreads();
        float acc = b1[d];
#pragma unroll
        for (int k = 0; k < 14; k++) acc = fmaf(xs[grp][k], w1[d * 15 + k], acc);
        g_P[n * HID + d] = acc;
    }
}

// ---------------- edge MLP + scatter-add ------------------------------------
// 128 threads / 128 edges. Stage B tiling: warp = 16-dim group; weight pairs
// are consecutive scalar floats read as broadcast ulonglong2 (NO duplication);
// h duplicated in-reg (4 pack2/k). acc axis = dim-pairs.
#define EDGE_DYN (32768 + 16384)
__global__ void __launch_bounds__(128, 4) edge_kernel(
    const void* __restrict__ ei, const float* __restrict__ eattr,
    const float* __restrict__ w1, const float* __restrict__ lng,
    const float* __restrict__ lnb, int nE) {
    extern __shared__ __align__(16) char dyn[];
    float* h1f = (float*)dyn;                 // 32KB [k][128]; overlaid later
    float* w2s = (float*)(dyn + 32768);       // 16KB [k][64] scalar w*g
    __shared__ __align__(16) float w1ls[64];
    __shared__ __align__(16) float As[64];
    __shared__ __align__(16) float Bcs[64];
    __shared__ __align__(16) float gs[64];
    __shared__ __align__(16) float bs[64];
    __shared__ __align__(8) float rst[128 * 2];
    __shared__ int sdst[128];

    int tid = threadIdx.x;
    {   // stage scalar weights: 1024 float4 over 128 threads
        const float4* wsrc = (const float4*)g_wgk;
        float4* wdst = (float4*)w2s;
#pragma unroll
        for (int i = 0; i < 8; i++) wdst[i * 128 + tid] = wsrc[i * 128 + tid];
    }
    if (tid < 64) {
        w1ls[tid] = w1[tid * 15 + 14];
        As[tid] = g_A[tid];
        Bcs[tid] = g_Bc[tid];
        gs[tid] = lng[tid];
        bs[tid] = lnb[tid];
    }
    long e = (long)blockIdx.x * 128 + tid;
    bool act = e < nE;
    int is64 = g_is64_ei;
    long src = 0;
    float a = 0.f;
    {
        long dl = -1;
        if (act) {
            src = ldidx(ei, e, is64);
            dl = ldidx(ei, (long)nE + e, is64);
            a = eattr[e];
        }
        sdst[tid] = (int)dl;
    }
    __syncthreads();

    // ---- Stage A: x = relu(P[src] + a*w1_last); stats; raw x -> smem ----
    {
        const float4* pr = (const float4*)(g_P + src * 64);
        float s1 = 0.f, q1 = 0.f;
#pragma unroll
        for (int g = 0; g < 16; g++) {
            float4 p = pr[g];
            float4 wl = ((const float4*)w1ls)[g];
            float x0 = fmaxf(fmaf(a, wl.x, p.x), 0.f);
            float x1 = fmaxf(fmaf(a, wl.y, p.y), 0.f);
            float x2 = fmaxf(fmaf(a, wl.z, p.z), 0.f);
            float x3 = fmaxf(fmaf(a, wl.w, p.w), 0.f);
            h1f[(4 * g + 0) * 128 + tid] = x0;
            h1f[(4 * g + 1) * 128 + tid] = x1;
            h1f[(4 * g + 2) * 128 + tid] = x2;
            h1f[(4 * g + 3) * 128 + tid] = x3;
            s1 += (x0 + x1) + (x2 + x3);
            q1 = fmaf(x0, x0, q1); q1 = fmaf(x1, x1, q1);
            q1 = fmaf(x2, x2, q1); q1 = fmaf(x3, x3, q1);
        }
        float mean1 = s1 * (1.f / 64.f);
        float var1 = fmaf(-mean1, mean1, q1 * (1.f / 64.f));
        float r1 = rsqrtf(var1 + 1e-5f);
        rst[2 * tid] = r1;
        rst[2 * tid + 1] = -mean1 * r1;
    }
    __syncthreads();

    // ---- Stage B: acc over dim-pairs; w pairs native, h duplicated ----
    int lane = tid & 31, wrp = tid >> 5;
    ull acc[4][8];   // [edge 0..3][dim-pair 0..7], dims = wrp*16 + 2*jp (+1)
#pragma unroll
    for (int ee = 0; ee < 4; ee++)
#pragma unroll
        for (int jp = 0; jp < 8; jp++) acc[ee][jp] = 0ull;
    {
        const float4* hb4 = (const float4*)h1f;
        const float* wbase = w2s + wrp * 16;
#pragma unroll 8
        for (int k = 0; k < 64; k++) {
            float4 hv = hb4[k * 32 + lane];        // edges 4*lane..+3, coalesced
            ull h0 = pack2(hv.x, hv.x);
            ull h1 = pack2(hv.y, hv.y);
            ull h2 = pack2(hv.z, hv.z);
            ull h3 = pack2(hv.w, hv.w);
            const ulonglong2* wk = (const ulonglong2*)(wbase + k * 64);
            ulonglong2 wA = wk[0];   // dim pairs (0,1),(2,3)
            ulonglong2 wB = wk[1];   // (4,5),(6,7)
            ulonglong2 wC = wk[2];   // (8,9),(10,11)
            ulonglong2 wD = wk[3];   // (12,13),(14,15)
            ffma2(acc[0][0], wA.x, h0); ffma2(acc[1][0], wA.x, h1);
            ffma2(acc[2][0], wA.x, h2); ffma2(acc[3][0], wA.x, h3);
            ffma2(acc[0][1], wA.y, h0); ffma2(acc[1][1], wA.y, h1);
            ffma2(acc[2][1], wA.y, h2); ffma2(acc[3][1], wA.y, h3);
            ffma2(acc[0][2], wB.x, h0); ffma2(acc[1][2], wB.x, h1);
            ffma2(acc[2][2], wB.x, h2); ffma2(acc[3][2], wB.x, h3);
            ffma2(acc[0][3], wB.y, h0); ffma2(acc[1][3], wB.y, h1);
            ffma2(acc[2][3], wB.y, h2); ffma2(acc[3][3], wB.y, h3);
            ffma2(acc[0][4], wC.x, h0); ffma2(acc[1][4], wC.x, h1);
            ffma2(acc[2][4], wC.x, h2); ffma2(acc[3][4], wC.x, h3);
            ffma2(acc[0][5], wC.y, h0); ffma2(acc[1][5], wC.y, h1);
            ffma2(acc[2][5], wC.y, h2); ffma2(acc[3][5], wC.y, h3);
            ffma2(acc[0][6], wD.x, h0); ffma2(acc[1][6], wD.x, h1);
            ffma2(acc[2][6], wD.x, h2); ffma2(acc[3][6], wD.x, h3);
            ffma2(acc[0][7], wD.y, h0); ffma2(acc[1][7], wD.y, h1);
            ffma2(acc[2][7], wD.y, h2); ffma2(acc[3][7], wD.y, h3);
        }
    }

    // ---- Stage C: fold LN1 consts, stats, LN2, scatter ----
    // This thread owns edges 4*lane..+3 and dims wrp*16..+15.
    float Ar[16], Br[16];
    {
        const float4* ap = (const float4*)(As + wrp * 16);
        const float4* bp = (const float4*)(Bcs + wrp * 16);
#pragma unroll
        for (int u = 0; u < 4; u++) {
            float4 av = ap[u], bv = bp[u];
            Ar[4 * u] = av.x; Ar[4 * u + 1] = av.y; Ar[4 * u + 2] = av.z; Ar[4 * u + 3] = av.w;
            Br[4 * u] = bv.x; Br[4 * u + 1] = bv.y; Br[4 * u + 2] = bv.z; Br[4 * u + 3] = bv.w;
        }
    }
    float rr[4], mm[4];
    int dn[4];
#pragma unroll
    for (int i = 0; i < 4; i++) {
        rr[i] = rst[2 * (4 * lane + i)];
        mm[i] = rst[2 * (4 * lane + i) + 1];
        dn[i] = sdst[4 * lane + i];
    }
    float vv[4][16];
    float se[4] = {0.f, 0.f, 0.f, 0.f}, qe[4] = {0.f, 0.f, 0.f, 0.f};
#pragma unroll
    for (int ee = 0; ee < 4; ee++) {
#pragma unroll
        for (int jp = 0; jp < 8; jp++) {
            float lo, hi;
            unpack2(acc[ee][jp], lo, hi);
            int j0 = 2 * jp, j1 = 2 * jp + 1;
            float v0 = fmaxf(fmaf(rr[ee], lo, fmaf(mm[ee], Ar[j0], Br[j0])), 0.f);
            float v1 = fmaxf(fmaf(rr[ee], hi, fmaf(mm[ee], Ar[j1], Br[j1])), 0.f);
            vv[ee][j0] = v0;
            vv[ee][j1] = v1;
            se[ee] += v0 + v1;
            qe[ee] = fmaf(v0, v0, qe[ee]);
            qe[ee] = fmaf(v1, v1, qe[ee]);
        }
    }
    __syncthreads();   // h1f reads done; overlay partials
    float* ps = h1f;            // [4][128]
    float* pq = h1f + 512;      // [4][128]
#pragma unroll
    for (int i = 0; i < 4; i++) {
        ps[wrp * 128 + 4 * lane + i] = se[i];
        pq[wrp * 128 + 4 * lane + i] = qe[i];
    }
    __syncthreads();
    {
        float s = ps[tid] + ps[128 + tid] + ps[256 + tid] + ps[384 + tid];
        float q = pq[tid] + pq[128 + tid] + pq[256 + tid] + pq[384 + tid];
        float mean = s * (1.f / 64.f);
        float var = fmaf(-mean, mean, q * (1.f / 64.f));
        float r = rsqrtf(var + 1e-5f);
        rst[2 * tid] = r;
        rst[2 * tid + 1] = -mean * r;
    }
    __syncthreads();
    float gr[16], br[16];
    {
        const float4* gp = (const float4*)(gs + wrp * 16);
        const float4* bp = (const float4*)(bs + wrp * 16);
#pragma unroll
        for (int u = 0; u < 4; u++) {
            float4 gv = gp[u], bv = bp[u];
            gr[4 * u] = gv.x; gr[4 * u + 1] = gv.y; gr[4 * u + 2] = gv.z; gr[4 * u + 3] = gv.w;
            br[4 * u] = bv.x; br[4 * u + 1] = bv.y; br[4 * u + 2] = bv.z; br[4 * u + 3] = bv.w;
        }
    }
#pragma unroll
    for (int i = 0; i < 4; i++) {
        float r2 = rst[2 * (4 * lane + i)];
        float mr2 = rst[2 * (4 * lane + i) + 1];
        if (dn[i] >= 0) {
            float* p = g_agg + (long)dn[i] * 64 + wrp * 16;
#pragma unroll
            for (int u = 0; u < 4; u++) {
                float o0 = fmaf(fmaf(vv[i][4 * u], r2, mr2), gr[4 * u], br[4 * u]);
                float o1 = fmaf(fmaf(vv[i][4 * u + 1], r2, mr2), gr[4 * u + 1], br[4 * u + 1]);
                float o2 = fmaf(fmaf(vv[i][4 * u + 2], r2, mr2), gr[4 * u + 2], br[4 * u + 2]);
                float o3 = fmaf(fmaf(vv[i][4 * u + 3], r2, mr2), gr[4 * u + 3], br[4 * u + 3]);
                asm volatile("red.global.add.v4.f32 [%0], {%1,%2,%3,%4};"
                             :: "l"(p + 4 * u), "f"(o0), "f"(o1), "f"(o2), "f"(o3)
                             : "memory");
            }
        }
    }
}

// ---------------- qkv = h @ in_proj_w.T + b, 32 nodes/block ------------------
__global__ void __launch_bounds__(192) qkv_kernel(const float* __restrict__ w,
                                                  const float* __restrict__ b, int N) {
    __shared__ __align__(16) float hs[32 * 64];
    int tid = threadIdx.x;
    int n0 = blockIdx.x * 32;
    for (int i = tid; i < 32 * 64 / 4; i += 192)
        ((float4*)hs)[i] = ((const float4*)(g_agg + n0 * 64))[i];
    float wr[64];
    {
        const float4* p4 = (const float4*)(w + tid * 64);
#pragma unroll
        for (int k = 0; k < 16; k++) {
            float4 f = p4[k];
            wr[4 * k] = f.x; wr[4 * k + 1] = f.y; wr[4 * k + 2] = f.z; wr[4 * k + 3] = f.w;
        }
    }
    float br = b[tid];
    __syncthreads();
    int sec = tid / 64, wi = tid % 64, hh = wi / 16, dd = wi % 16;
    float* dst = sec == 0 ? g_q : (sec == 1 ? g_k : g_v);
#pragma unroll 4
    for (int nn = 0; nn < 32; nn++) {
        float acc = br;
#pragma unroll
        for (int k = 0; k < 16; k++) {
            float4 h = *(const float4*)&hs[nn * 64 + 4 * k];
            acc = fmaf(wr[4 * k], h.x, acc);
            acc = fmaf(wr[4 * k + 1], h.y, acc);
            acc = fmaf(wr[4 * k + 2], h.z, acc);
            acc = fmaf(wr[4 * k + 3], h.w, acc);
        }
        dst[hh * N * 16 + (n0 + nn) * 16 + dd] = acc;
    }
}

// ---------------- flash attention, f32x2, chunked branchless rescale --------
__global__ void __launch_bounds__(128) attn_kernel(int N) {
    int hh = blockIdx.y;
    int part = threadIdx.x >> 5;
    int lane = threadIdx.x & 31;
    int qi = blockIdx.x * 32 + lane;
    const float* Q = g_q + hh * N * 16;
    const float* K = g_k + hh * N * 16;
    const float* V = g_v + hh * N * 16;

    __shared__ __align__(16) float Ks[4][64 * 16];
    __shared__ __align__(16) float Vs[4][64 * 16];
    __shared__ float mrg[3][32][18];

    ull q2[8];
    {
        const float4* qp = (const float4*)(Q + qi * 16);
#pragma unroll
        for (int u = 0; u < 4; u++) {
            float4 f = qp[u];
            q2[2 * u] = pack2(f.x * 0.25f, f.y * 0.25f);
            q2[2 * u + 1] = pack2(f.z * 0.25f, f.w * 0.25f);
        }
    }
    ull o2[8];
#pragma unroll
    for (int u = 0; u < 8; u++) o2[u] = 0ull;
    float m = -1e30f, l = 0.f;

    int j0 = part * (N >> 2);
    for (int kt = 0; kt < (N >> 2); kt += 64) {
        {
            const float4* ksrc = (const float4*)(K + (j0 + kt) * 16);
            const float4* vsrc = (const float4*)(V + (j0 + kt) * 16);
            float4* kdst = (float4*)Ks[part];
            float4* vdst = (float4*)Vs[part];
#pragma unroll
            for (int u = 0; u < 8; u++) {
                kdst[u * 32 + lane] = ksrc[u * 32 + lane];
                vdst[u * 32 + lane] = vsrc[u * 32 + lane];
            }
        }
        __syncwarp();
        for (int c = 0; c < 4; c++) {
            float s[16];
#pragma unroll
            for (int jj = 0; jj < 16; jj++) {
                int j = c * 16 + jj;
                const ulonglong2* kr = (const ulonglong2*)&Ks[part][j * 16];
                ulonglong2 ka = kr[0], kb = kr[1], kc = kr[2], kd = kr[3];
                ull s2 = mul2(q2[0], ka.x);
                ffma2(s2, q2[1], ka.y);
                ffma2(s2, q2[2], kb.x);
                ffma2(s2, q2[3], kb.y);
                ffma2(s2, q2[4], kc.x);
                ffma2(s2, q2[5], kc.y);
                ffma2(s2, q2[6], kd.x);
                ffma2(s2, q2[7], kd.y);
                float slo, shi;
                unpack2(s2, slo, shi);
                s[jj] = slo + shi;
            }
            float tm = s[0];
#pragma unroll
            for (int jj = 1; jj < 16; jj++) tm = fmaxf(tm, s[jj]);
            float nm = fmaxf(m, tm);
            float corr = __expf(m - nm);
            m = nm;
            l *= corr;
            ull c2 = pack2(corr, corr);
#pragma unroll
            for (int u = 0; u < 8; u++) o2[u] = mul2(o2[u], c2);
#pragma unroll
            for (int jj = 0; jj < 16; jj++) {
                int j = c * 16 + jj;
                float p = __expf(s[jj] - m);
                l += p;
                ull p2 = pack2(p, p);
                const ulonglong2* vr = (const ulonglong2*)&Vs[part][j * 16];
                ulonglong2 va = vr[0], vb = vr[1], vc = vr[2], vd = vr[3];
                ffma2(o2[0], p2, va.x);
                ffma2(o2[1], p2, va.y);
                ffma2(o2[2], p2, vb.x);
                ffma2(o2[3], p2, vb.y);
                ffma2(o2[4], p2, vc.x);
                ffma2(o2[5], p2, vc.y);
                ffma2(o2[6], p2, vd.x);
                ffma2(o2[7], p2, vd.y);
            }
        }
        __syncwarp();
    }

    if (part != 0) {
        float* d = &mrg[part - 1][lane][0];
        d[0] = m;
        d[1] = l;
#pragma unroll
        for (int u = 0; u < 8; u++) {
            float lo, hi;
            unpack2(o2[u], lo, hi);
            d[2 + 2 * u] = lo;
            d[3 + 2 * u] = hi;
        }
    }
    __syncthreads();
    if (part == 0) {
        float M = m;
#pragma unroll
        for (int p2i = 0; p2i < 3; p2i++) M = fmaxf(M, mrg[p2i][lane][0]);
        float c0 = __expf(m - M);
        float L = l * c0;
        float o[16];
#pragma unroll
        for (int u = 0; u < 8; u++) {
            float lo, hi;
            unpack2(o2[u], lo, hi);
            o[2 * u] = lo * c0;
            o[2 * u + 1] = hi * c0;
        }
#pragma unroll
        for (int p2i = 0; p2i < 3; p2i++) {
            const float* sp = &mrg[p2i][lane][0];
            float cp = __expf(sp[0] - M);
            L = fmaf(sp[1], cp, L);
#pragma unroll
            for (int c = 0; c < 16; c++) o[c] = fmaf(sp[2 + c], cp, o[c]);
        }
        float inv = 1.f / L;
#pragma unroll
        for (int c = 0; c < 16; c++) g_obuf[qi * 64 + hh * 16 + c] = o[c] * inv;
    }
}

// ---------------- out_proj + residual + LN + final linear --------------------
__global__ void __launch_bounds__(128) epi_kernel(
    const float* __restrict__ opw, const float* __restrict__ opb,
    const float* __restrict__ ang, const float* __restrict__ anb,
    const float* __restrict__ ow, const float* __restrict__ ob,
    float* __restrict__ out) {
    int tid = threadIdx.x;
    int d = tid & 63, g = tid >> 6;
    int n0 = blockIdx.x * 8;
    __shared__ __align__(16) float os[8 * 64];
    __shared__ __align__(16) float ts[8 * 64];
    __shared__ float ps[8][16], pq[8][16];
    __shared__ float mv[8][2];

    for (int i = tid; i < 8 * 64; i += 128) os[i] = g_obuf[n0 * 64 + i];
    float wr[64];
    {
        const float4* p4 = (const float4*)(opw + d * 64);
#pragma unroll
        for (int k = 0; k < 16; k++) {
            float4 f = p4[k];
            wr[4 * k] = f.x; wr[4 * k + 1] = f.y; wr[4 * k + 2] = f.z; wr[4 * k + 3] = f.w;
        }
    }
    float bb = opb[d];
    __syncthreads();
#pragma unroll
    for (int ni = 0; ni < 4; ni++) {
        int nn = g * 4 + ni;
        float acc = bb;
#pragma unroll
        for (int k = 0; k < 16; k++) {
            float4 h = *(const float4*)&os[nn * 64 + 4 * k];
            acc = fmaf(wr[4 * k], h.x, acc);
            acc = fmaf(wr[4 * k + 1], h.y, acc);
            acc = fmaf(wr[4 * k + 2], h.z, acc);
            acc = fmaf(wr[4 * k + 3], h.w, acc);
        }
        ts[nn * 64 + d] = g_agg[(n0 + nn) * 64 + d] + acc;
    }
    __syncthreads();
    {
        int n = tid >> 4, sg = tid & 15;
        float s = 0.f, qq = 0.f;
#pragma unroll
        for (int t = 0; t < 4; t++) {
            float v2 = ts[n * 64 + sg * 4 + t];
            s += v2; qq += v2 * v2;
        }
        ps[n][sg] = s; pq[n][sg] = qq;
    }
    __syncthreads();
    if (tid < 8) {
        float s = 0.f, qq = 0.f;
#pragma unroll
        for (int t = 0; t < 16; t++) { s += ps[tid][t]; qq += pq[tid][t]; }
        float mean = s * (1.f / 64.f);
        float var = qq * (1.f / 64.f) - mean * mean;
        mv[tid][0] = mean;
        mv[tid][1] = rsqrtf(var + 1e-5f);
    }
    __syncthreads();
    float gg = ang[d], gb = anb[d];
#pragma unroll
    for (int ni = 0; ni < 4; ni++) {
        int nn = g * 4 + ni;
        ts[nn * 64 + d] = (ts[nn * 64 + d] - mv[nn][0]) * mv[nn][1] * gg + gb;
    }
    {
        const float4* p4 = (const float4*)(ow + d * 64);
#pragma unroll
        for (int k = 0; k < 16; k++) {
            float4 f = p4[k];
            wr[4 * k] = f.x; wr[4 * k + 1] = f.y; wr[4 * k + 2] = f.z; wr[4 * k + 3] = f.w;
        }
    }
    float bo = ob[d];
    __syncthreads();
#pragma unroll
    for (int ni = 0; ni < 4; ni++) {
        int nn = g * 4 + ni;
        float acc = bo;
#pragma unroll
        for (int k = 0; k < 16; k++) {
            float4 h = *(const float4*)&ts[nn * 64 + 4 * k];
            acc = fmaf(wr[4 * k], h.x, acc);
            acc = fmaf(wr[4 * k + 1], h.y, acc);
            acc = fmaf(wr[4 * k + 2], h.z, acc);
            acc = fmaf(wr[4 * k + 3], h.w, acc);
        }
        out[(n0 + nn) * 64 + d] = acc;
    }
}

// ---------------- launch ----------------
extern "C" void kernel_launch(void* const* d_in, const int* in_sizes, int n_in,
                              void* d_out, int out_size) {
    const float* x        = (const float*)d_in[0];
    const float* eattr    = (const float*)d_in[1];
    const float* emb      = (const float*)d_in[2];
    const float* lin1_w   = (const float*)d_in[3];
    const float* lin1_b   = (const float*)d_in[4];
    const float* lay_w    = (const float*)d_in[5];
    const float* lay_b    = (const float*)d_in[6];
    const float* ln_g     = (const float*)d_in[7];
    const float* ln_b     = (const float*)d_in[8];
    const float* in_proj_w  = (const float*)d_in[9];
    const float* in_proj_b  = (const float*)d_in[10];
    const float* out_proj_w = (const float*)d_in[11];
    const float* out_proj_b = (const float*)d_in[12];
    const float* an_g     = (const float*)d_in[13];
    const float* an_b     = (const float*)d_in[14];
    const float* out_w    = (const float*)d_in[15];
    const float* out_b    = (const float*)d_in[16];
    const void*  ei       = d_in[17];
    const void*  ety      = d_in[18];

    int E = in_sizes[1];
    int N = in_sizes[0] / 6;

    cudaFuncSetAttribute(edge_kernel, cudaFuncAttributeMaxDynamicSharedMemorySize,
                         EDGE_DYN);

    detectAB_kernel<<<1, 64>>>((const unsigned*)ei, (const unsigned*)ety,
                               lay_w, ln_g, ln_b, lay_b);
    setup_kernel<<<N / 16 + 16 + N / 4, 256>>>(x, emb, lin1_w, lin1_b, ety,
                                               lay_w, ln_g, N);
    edge_kernel<<<(E + 127) / 128, 128, EDGE_DYN>>>(ei, eattr, lin1_w, ln_g,
                                                    ln_b, E);
    qkv_kernel<<<N / 32, 192>>>(in_proj_w, in_proj_b, N);
    attn_kernel<<<dim3(N / 32, 4), 128>>>(N);
    epi_kernel<<<N / 8, 128>>>(out_proj_w, out_proj_b, an_g, an_b, out_w, out_b,
                               (float*)d_out);
}